// round 1
// baseline (speedup 1.0000x reference)
#include <cuda_runtime.h>
#include <math_constants.h>

// Problem constants
#define B 8
#define S 2048
#define E 1024
#define D 64
#define ROWS (B * S)          // 16384

// Scratch for projected q,k,v: [3][16384][64] f32 = 12 MB
__device__ float g_qkv[3][(size_t)ROWS * D];

// ---------------------------------------------------------------------------
// Kernel 1: fused projection. z=0 -> k (Wk), z=1 -> q (Wq), z=2 -> v (Wv)
// Tile: 128 rows x 64 cols, BK=16, 256 threads, 8x4 per thread.
// ---------------------------------------------------------------------------
__global__ __launch_bounds__(256) void proj_kernel(
    const float* __restrict__ seq,
    const float* __restrict__ Wk,
    const float* __restrict__ Wq,
    const float* __restrict__ Wv)
{
    const float* W = (blockIdx.z == 0) ? Wk : (blockIdx.z == 1) ? Wq : Wv;
    float* out = g_qkv[blockIdx.z];

    __shared__ float As[16][128];   // [k][row] (transposed)
    __shared__ float Bs[16][64];    // [k][col]

    const int tid = threadIdx.x;
    const int row0 = blockIdx.x * 128;
    const int ty = tid / 16;        // 0..15 -> 8-row group
    const int tx = tid % 16;        // 0..15 -> 4-col group

    float acc[8][4];
#pragma unroll
    for (int i = 0; i < 8; i++)
#pragma unroll
        for (int j = 0; j < 4; j++) acc[i][j] = 0.f;

    for (int k0 = 0; k0 < E; k0 += 16) {
        // Load A tile 128x16 (512 float4, 2 per thread), store transposed
#pragma unroll
        for (int i = 0; i < 2; i++) {
            int idx = tid + i * 256;          // float4 index
            int r = idx >> 2;                 // row 0..127
            int c4 = idx & 3;                 // which float4 in 16 cols
            float4 v = *reinterpret_cast<const float4*>(
                &seq[(size_t)(row0 + r) * E + k0 + c4 * 4]);
            As[c4 * 4 + 0][r] = v.x;
            As[c4 * 4 + 1][r] = v.y;
            As[c4 * 4 + 2][r] = v.z;
            As[c4 * 4 + 3][r] = v.w;
        }
        // Load B tile 16x64 (256 float4, 1 per thread)
        {
            int r = tid / 16;
            int c4 = tid % 16;
            float4 v = *reinterpret_cast<const float4*>(
                &W[(size_t)(k0 + r) * D + c4 * 4]);
            Bs[r][c4 * 4 + 0] = v.x;
            Bs[r][c4 * 4 + 1] = v.y;
            Bs[r][c4 * 4 + 2] = v.z;
            Bs[r][c4 * 4 + 3] = v.w;
        }
        __syncthreads();

#pragma unroll
        for (int kk = 0; kk < 16; kk++) {
            float4 a0 = *reinterpret_cast<const float4*>(&As[kk][ty * 8]);
            float4 a1 = *reinterpret_cast<const float4*>(&As[kk][ty * 8 + 4]);
            float4 b0 = *reinterpret_cast<const float4*>(&Bs[kk][tx * 4]);
            float a[8] = {a0.x, a0.y, a0.z, a0.w, a1.x, a1.y, a1.z, a1.w};
            float bb[4] = {b0.x, b0.y, b0.z, b0.w};
#pragma unroll
            for (int i = 0; i < 8; i++)
#pragma unroll
                for (int j = 0; j < 4; j++) acc[i][j] = fmaf(a[i], bb[j], acc[i][j]);
        }
        __syncthreads();
    }

#pragma unroll
    for (int i = 0; i < 8; i++) {
        float4 v = make_float4(acc[i][0], acc[i][1], acc[i][2], acc[i][3]);
        *reinterpret_cast<float4*>(
            &out[(size_t)(row0 + ty * 8 + i) * D + tx * 4]) = v;
    }
}

// ---------------------------------------------------------------------------
// Kernel 2: scores = (Q K^T) * D^-0.5 with causal mask -> attn region (raw).
// Grid (16,16,8): x = k-tile, y = q-tile, z = batch. 128x128 tile, 8x8/thread.
// Strictly-upper tiles write zeros (d_out is poisoned).
// ---------------------------------------------------------------------------
__global__ __launch_bounds__(256) void scores_kernel(float* __restrict__ attn)
{
    const int b = blockIdx.z;
    const int qt = blockIdx.y;
    const int kt = blockIdx.x;
    const int q0 = qt * 128;
    const int k0 = kt * 128;
    const int tid = threadIdx.x;
    float* arow = attn + (size_t)b * S * S;

    if (kt > qt) {
        // Zero 128x128 tile: 4096 float4, 16 per thread
#pragma unroll
        for (int i = 0; i < 16; i++) {
            int idx = tid + i * 256;
            int r = idx >> 5;          // 0..127
            int c4 = idx & 31;         // 0..31
            *reinterpret_cast<float4*>(
                &arow[(size_t)(q0 + r) * S + k0 + c4 * 4]) =
                make_float4(0.f, 0.f, 0.f, 0.f);
        }
        return;
    }

    const float* Q = g_qkv[1] + (size_t)(b * S + q0) * D;
    const float* K = g_qkv[0] + (size_t)(b * S + k0) * D;

    __shared__ float Qs[32][128];   // [d][row]
    __shared__ float Ks[32][128];   // [d][col]

    const int ty = tid / 16;
    const int tx = tid % 16;

    float acc[8][8];
#pragma unroll
    for (int i = 0; i < 8; i++)
#pragma unroll
        for (int j = 0; j < 8; j++) acc[i][j] = 0.f;

    for (int d0 = 0; d0 < D; d0 += 32) {
        // Load Q tile 128x32 transposed: 1024 float4, 4 per thread
#pragma unroll
        for (int i = 0; i < 4; i++) {
            int idx = tid + i * 256;
            int r = idx >> 3;
            int c4 = idx & 7;
            float4 v = *reinterpret_cast<const float4*>(
                &Q[(size_t)r * D + d0 + c4 * 4]);
            Qs[c4 * 4 + 0][r] = v.x;
            Qs[c4 * 4 + 1][r] = v.y;
            Qs[c4 * 4 + 2][r] = v.z;
            Qs[c4 * 4 + 3][r] = v.w;
        }
#pragma unroll
        for (int i = 0; i < 4; i++) {
            int idx = tid + i * 256;
            int r = idx >> 3;
            int c4 = idx & 7;
            float4 v = *reinterpret_cast<const float4*>(
                &K[(size_t)r * D + d0 + c4 * 4]);
            Ks[c4 * 4 + 0][r] = v.x;
            Ks[c4 * 4 + 1][r] = v.y;
            Ks[c4 * 4 + 2][r] = v.z;
            Ks[c4 * 4 + 3][r] = v.w;
        }
        __syncthreads();

#pragma unroll
        for (int kk = 0; kk < 32; kk++) {
            float4 a0 = *reinterpret_cast<const float4*>(&Qs[kk][ty * 8]);
            float4 a1 = *reinterpret_cast<const float4*>(&Qs[kk][ty * 8 + 4]);
            float4 b0 = *reinterpret_cast<const float4*>(&Ks[kk][tx * 8]);
            float4 b1 = *reinterpret_cast<const float4*>(&Ks[kk][tx * 8 + 4]);
            float a[8] = {a0.x, a0.y, a0.z, a0.w, a1.x, a1.y, a1.z, a1.w};
            float bb[8] = {b0.x, b0.y, b0.z, b0.w, b1.x, b1.y, b1.z, b1.w};
#pragma unroll
            for (int i = 0; i < 8; i++)
#pragma unroll
                for (int j = 0; j < 8; j++)
                    acc[i][j] = fmaf(a[i], bb[j], acc[i][j]);
        }
        __syncthreads();
    }

    const float scale = 0.125f;   // D^-0.5, D=64
#pragma unroll
    for (int i = 0; i < 8; i++) {
        int q = q0 + ty * 8 + i;
#pragma unroll
        for (int j4 = 0; j4 < 2; j4++) {
            float v[4];
#pragma unroll
            for (int j = 0; j < 4; j++) {
                int k = k0 + tx * 8 + j4 * 4 + j;
                v[j] = (k <= q) ? acc[i][j4 * 4 + j] * scale : 0.f;
            }
            *reinterpret_cast<float4*>(
                &arow[(size_t)q * S + k0 + tx * 8 + j4 * 4]) =
                make_float4(v[0], v[1], v[2], v[3]);
        }
    }
}

// ---------------------------------------------------------------------------
// Kernel 3: in-place causal row softmax. One block per row, row cached in smem.
// ---------------------------------------------------------------------------
__global__ __launch_bounds__(256) void softmax_kernel(float* __restrict__ attn)
{
    const int row = blockIdx.x;             // 0..16383
    const int b = row / S;
    const int i = row % S;
    float* p = attn + (size_t)b * S * S + (size_t)i * S;
    const int L = i + 1;

    __shared__ float buf[S];
    __shared__ float red[8];

    const int tid = threadIdx.x;
    const int lane = tid & 31;
    const int w = tid >> 5;

    float mx = -CUDART_INF_F;
    for (int j = tid; j < L; j += 256) {
        float v = p[j];
        buf[j] = v;
        mx = fmaxf(mx, v);
    }
    // block max
#pragma unroll
    for (int o = 16; o; o >>= 1) mx = fmaxf(mx, __shfl_xor_sync(0xffffffffu, mx, o));
    if (lane == 0) red[w] = mx;
    __syncthreads();
    if (w == 0) {
        float x = (lane < 8) ? red[lane] : -CUDART_INF_F;
#pragma unroll
        for (int o = 4; o; o >>= 1) x = fmaxf(x, __shfl_xor_sync(0xffffffffu, x, o));
        if (lane == 0) red[0] = x;
    }
    __syncthreads();
    mx = red[0];
    __syncthreads();

    float sum = 0.f;
    for (int j = tid; j < L; j += 256) {
        float e = __expf(buf[j] - mx);
        buf[j] = e;
        sum += e;
    }
#pragma unroll
    for (int o = 16; o; o >>= 1) sum += __shfl_xor_sync(0xffffffffu, sum, o);
    if (lane == 0) red[w] = sum;
    __syncthreads();
    if (w == 0) {
        float x = (lane < 8) ? red[lane] : 0.f;
#pragma unroll
        for (int o = 4; o; o >>= 1) x += __shfl_xor_sync(0xffffffffu, x, o);
        if (lane == 0) red[0] = x;
    }
    __syncthreads();
    const float inv = 1.f / red[0];

    for (int j = tid; j < L; j += 256) p[j] = buf[j] * inv;
}

// ---------------------------------------------------------------------------
// Kernel 4: out = attn @ V (causal: K-loop truncated at (qt+1)*128).
// Grid (1,16,8). Tile 128x64, BK=32, 256 threads, 8x4 per thread.
// ---------------------------------------------------------------------------
__global__ __launch_bounds__(256) void out_kernel(
    const float* __restrict__ attn_full, float* __restrict__ out)
{
    const int b = blockIdx.z;
    const int qt = blockIdx.y;
    const int q0 = qt * 128;
    const float* attn = attn_full + (size_t)b * S * S;
    const float* V = g_qkv[2] + (size_t)b * S * D;

    __shared__ float As[32][132];   // [k][row], padded
    __shared__ float Vs[32][64];    // [k][col]

    const int tid = threadIdx.x;
    const int ty = tid / 16;
    const int tx = tid % 16;

    float acc[8][4];
#pragma unroll
    for (int i = 0; i < 8; i++)
#pragma unroll
        for (int j = 0; j < 4; j++) acc[i][j] = 0.f;

    const int kmax = (qt + 1) * 128;
    for (int kk0 = 0; kk0 < kmax; kk0 += 32) {
        // attn tile 128x32 transposed: 1024 float4, 4 per thread
#pragma unroll
        for (int i = 0; i < 4; i++) {
            int idx = tid + i * 256;
            int r = idx >> 3;
            int c4 = idx & 7;
            float4 v = *reinterpret_cast<const float4*>(
                &attn[(size_t)(q0 + r) * S + kk0 + c4 * 4]);
            As[c4 * 4 + 0][r] = v.x;
            As[c4 * 4 + 1][r] = v.y;
            As[c4 * 4 + 2][r] = v.z;
            As[c4 * 4 + 3][r] = v.w;
        }
        // V tile 32x64: 512 float4, 2 per thread
#pragma unroll
        for (int i = 0; i < 2; i++) {
            int idx = tid + i * 256;
            int r = idx >> 4;
            int c4 = idx & 15;
            float4 v = *reinterpret_cast<const float4*>(
                &V[(size_t)(kk0 + r) * D + c4 * 4]);
            Vs[r][c4 * 4 + 0] = v.x;
            Vs[r][c4 * 4 + 1] = v.y;
            Vs[r][c4 * 4 + 2] = v.z;
            Vs[r][c4 * 4 + 3] = v.w;
        }
        __syncthreads();

#pragma unroll
        for (int kk = 0; kk < 32; kk++) {
            float4 a0 = *reinterpret_cast<const float4*>(&As[kk][ty * 8]);
            float4 a1 = *reinterpret_cast<const float4*>(&As[kk][ty * 8 + 4]);
            float4 b0 = *reinterpret_cast<const float4*>(&Vs[kk][tx * 4]);
            float a[8] = {a0.x, a0.y, a0.z, a0.w, a1.x, a1.y, a1.z, a1.w};
            float bb[4] = {b0.x, b0.y, b0.z, b0.w};
#pragma unroll
            for (int i = 0; i < 8; i++)
#pragma unroll
                for (int j = 0; j < 4; j++)
                    acc[i][j] = fmaf(a[i], bb[j], acc[i][j]);
        }
        __syncthreads();
    }

#pragma unroll
    for (int i = 0; i < 8; i++) {
        float4 v = make_float4(acc[i][0], acc[i][1], acc[i][2], acc[i][3]);
        *reinterpret_cast<float4*>(
            &out[(size_t)(b * S + q0 + ty * 8 + i) * D + tx * 4]) = v;
    }
}

// ---------------------------------------------------------------------------
extern "C" void kernel_launch(void* const* d_in, const int* in_sizes, int n_in,
                              void* d_out, int out_size)
{
    const float* seq = (const float*)d_in[0];
    const float* Wk  = (const float*)d_in[1];
    const float* Wq  = (const float*)d_in[2];
    const float* Wv  = (const float*)d_in[3];

    float* out  = (float*)d_out;                        // [B,S,D]
    float* attn = (float*)d_out + (size_t)B * S * D;    // [B,S,S]

    proj_kernel<<<dim3(ROWS / 128, 1, 3), 256>>>(seq, Wk, Wq, Wv);
    scores_kernel<<<dim3(S / 128, S / 128, B), 256>>>(attn);
    softmax_kernel<<<ROWS, 256>>>(attn);
    out_kernel<<<dim3(1, S / 128, B), 256>>>(attn, out);
}

// round 2
// speedup vs baseline: 1.2507x; 1.2507x over previous
#include <cuda_runtime.h>
#include <cuda_bf16.h>
#include <math_constants.h>
#include <stdint.h>

#define B 8
#define S 2048
#define E 1024
#define D 64
#define NROWS (B * S)

// Scratch: K, Q in [row][d]; V pre-transposed [b][d][s]
__device__ float g_k[(size_t)NROWS * D];
__device__ float g_q[(size_t)NROWS * D];
__device__ float g_vt[(size_t)B * D * S];

// ---------------------------------------------------------------------------
// helpers
// ---------------------------------------------------------------------------
__device__ __forceinline__ void split2(float x, __nv_bfloat16& h, __nv_bfloat16& l) {
    h = __float2bfloat16_rn(x);
    l = __float2bfloat16_rn(x - __bfloat162float(h));
}
__device__ __forceinline__ __nv_bfloat162 mk2(__nv_bfloat16 a, __nv_bfloat16 b) {
    __nv_bfloat162 t; t.x = a; t.y = b; return t;
}

__device__ __forceinline__ void mma16816(float* d, uint32_t a0, uint32_t a1,
                                         uint32_t a2, uint32_t a3,
                                         uint32_t b0, uint32_t b1) {
    asm volatile(
        "mma.sync.aligned.m16n8k16.row.col.f32.bf16.bf16.f32 "
        "{%0,%1,%2,%3},{%4,%5,%6,%7},{%8,%9},{%0,%1,%2,%3};"
        : "+f"(d[0]), "+f"(d[1]), "+f"(d[2]), "+f"(d[3])
        : "r"(a0), "r"(a1), "r"(a2), "r"(a3), "r"(b0), "r"(b1));
}

// ---------------------------------------------------------------------------
// Kernel 1: projections. z=0 -> K, z=1 -> Q, z=2 -> V (transposed store).
// Block: 64 rows x 64 cols, BK=64, 256 threads, warps 4(m) x 2(n), warp 16x32.
// ---------------------------------------------------------------------------
__global__ __launch_bounds__(256) void proj_mma(
    const float* __restrict__ seq,
    const float* __restrict__ Wk,
    const float* __restrict__ Wq,
    const float* __restrict__ Wv)
{
    const int z = blockIdx.z;
    const float* W = (z == 0) ? Wk : (z == 1) ? Wq : Wv;
    const int row0 = blockIdx.x * 64;

    __shared__ __nv_bfloat16 Ah[64][72], Al[64][72];
    __shared__ __nv_bfloat16 Bth[64][66], Btl[64][66];   // [n=d][k], transposed

    const int tid = threadIdx.x;
    const int lane = tid & 31, wid = tid >> 5;
    const int wm = wid >> 1, wn = wid & 1;
    const int qr = lane >> 2, qc = lane & 3;

    float acc[4][4];
#pragma unroll
    for (int i = 0; i < 4; i++)
#pragma unroll
        for (int j = 0; j < 4; j++) acc[i][j] = 0.f;

    for (int k0 = 0; k0 < E; k0 += 64) {
        // A tile 64x64: 1024 float4, 4 per thread
#pragma unroll
        for (int i = 0; i < 4; i++) {
            int idx = tid + i * 256;
            int r = idx >> 4, c = (idx & 15) * 4;
            float4 v = *reinterpret_cast<const float4*>(
                &seq[(size_t)(row0 + r) * E + k0 + c]);
            __nv_bfloat16 h0, h1, h2, h3, l0, l1, l2, l3;
            split2(v.x, h0, l0); split2(v.y, h1, l1);
            split2(v.z, h2, l2); split2(v.w, h3, l3);
            *reinterpret_cast<__nv_bfloat162*>(&Ah[r][c])     = mk2(h0, h1);
            *reinterpret_cast<__nv_bfloat162*>(&Ah[r][c + 2]) = mk2(h2, h3);
            *reinterpret_cast<__nv_bfloat162*>(&Al[r][c])     = mk2(l0, l1);
            *reinterpret_cast<__nv_bfloat162*>(&Al[r][c + 2]) = mk2(l2, l3);
        }
        // B tile: W[k0+r][c] -> Bt[c][r] (transpose)
#pragma unroll
        for (int i = 0; i < 4; i++) {
            int idx = tid + i * 256;
            int r = idx >> 4, c = (idx & 15) * 4;
            float4 v = *reinterpret_cast<const float4*>(
                &W[(size_t)(k0 + r) * D + c]);
            __nv_bfloat16 h, l;
            split2(v.x, h, l); Bth[c + 0][r] = h; Btl[c + 0][r] = l;
            split2(v.y, h, l); Bth[c + 1][r] = h; Btl[c + 1][r] = l;
            split2(v.z, h, l); Bth[c + 2][r] = h; Btl[c + 2][r] = l;
            split2(v.w, h, l); Bth[c + 3][r] = h; Btl[c + 3][r] = l;
        }
        __syncthreads();

#pragma unroll
        for (int kc = 0; kc < 4; kc++) {
            int kk = kc * 16;
            int ar = wm * 16 + qr;
            uint32_t ah0 = *reinterpret_cast<const uint32_t*>(&Ah[ar][kk + 2 * qc]);
            uint32_t ah1 = *reinterpret_cast<const uint32_t*>(&Ah[ar + 8][kk + 2 * qc]);
            uint32_t ah2 = *reinterpret_cast<const uint32_t*>(&Ah[ar][kk + 8 + 2 * qc]);
            uint32_t ah3 = *reinterpret_cast<const uint32_t*>(&Ah[ar + 8][kk + 8 + 2 * qc]);
            uint32_t al0 = *reinterpret_cast<const uint32_t*>(&Al[ar][kk + 2 * qc]);
            uint32_t al1 = *reinterpret_cast<const uint32_t*>(&Al[ar + 8][kk + 2 * qc]);
            uint32_t al2 = *reinterpret_cast<const uint32_t*>(&Al[ar][kk + 8 + 2 * qc]);
            uint32_t al3 = *reinterpret_cast<const uint32_t*>(&Al[ar + 8][kk + 8 + 2 * qc]);
#pragma unroll
            for (int na = 0; na < 4; na++) {
                int nr = wn * 32 + na * 8 + qr;
                uint32_t bh0 = *reinterpret_cast<const uint32_t*>(&Bth[nr][kk + 2 * qc]);
                uint32_t bh1 = *reinterpret_cast<const uint32_t*>(&Bth[nr][kk + 8 + 2 * qc]);
                uint32_t bl0 = *reinterpret_cast<const uint32_t*>(&Btl[nr][kk + 2 * qc]);
                uint32_t bl1 = *reinterpret_cast<const uint32_t*>(&Btl[nr][kk + 8 + 2 * qc]);
                mma16816(acc[na], ah0, ah1, ah2, ah3, bh0, bh1);
                mma16816(acc[na], ah0, ah1, ah2, ah3, bl0, bl1);
                mma16816(acc[na], al0, al1, al2, al3, bh0, bh1);
            }
        }
        __syncthreads();
    }

    const int grow = row0 + wm * 16 + qr;
    if (z == 2) {
        const int b = row0 >> 11;
        const int s1 = grow & 2047, s2 = (grow + 8) & 2047;
#pragma unroll
        for (int na = 0; na < 4; na++) {
            int col = wn * 32 + na * 8 + 2 * qc;
            g_vt[((size_t)(b * D + col)) * S + s1]     = acc[na][0];
            g_vt[((size_t)(b * D + col + 1)) * S + s1] = acc[na][1];
            g_vt[((size_t)(b * D + col)) * S + s2]     = acc[na][2];
            g_vt[((size_t)(b * D + col + 1)) * S + s2] = acc[na][3];
        }
    } else {
        float* outp = (z == 0) ? g_k : g_q;
#pragma unroll
        for (int na = 0; na < 4; na++) {
            int col = wn * 32 + na * 8 + 2 * qc;
            *reinterpret_cast<float2*>(&outp[(size_t)grow * D + col]) =
                make_float2(acc[na][0], acc[na][1]);
            *reinterpret_cast<float2*>(&outp[(size_t)(grow + 8) * D + col]) =
                make_float2(acc[na][2], acc[na][3]);
        }
    }
}

// ---------------------------------------------------------------------------
// Kernel 2: scores = (Q K^T) * 0.125 with causal mask -> attn (raw scores).
// Block 128x128, warps 2(m) x 4(n) -> warp 64x32. BK=32. Upper tiles: zeros.
// ---------------------------------------------------------------------------
__global__ __launch_bounds__(256) void scores_mma(float* __restrict__ attn)
{
    const int b = blockIdx.z, qt = blockIdx.y, kt = blockIdx.x;
    const int q0 = qt * 128, k0 = kt * 128;
    float* arow = attn + (size_t)b * S * S;
    const int tid = threadIdx.x;

    if (kt > qt) {
#pragma unroll
        for (int i = 0; i < 16; i++) {
            int idx = tid + i * 256;
            int r = idx >> 5, c = (idx & 31) * 4;
            *reinterpret_cast<float4*>(&arow[(size_t)(q0 + r) * S + k0 + c]) =
                make_float4(0.f, 0.f, 0.f, 0.f);
        }
        return;
    }

    __shared__ __nv_bfloat16 Qh[128][40], Ql[128][40];
    __shared__ __nv_bfloat16 Kh[128][40], Kl[128][40];

    const int lane = tid & 31, wid = tid >> 5;
    const int wm = wid >> 2, wn = wid & 3;
    const int qr = lane >> 2, qc = lane & 3;

    float acc[4][4][4];
#pragma unroll
    for (int a = 0; a < 4; a++)
#pragma unroll
        for (int c = 0; c < 4; c++)
#pragma unroll
            for (int e = 0; e < 4; e++) acc[a][c][e] = 0.f;

    const float* Qg = g_q + (size_t)(b * S + q0) * D;
    const float* Kg = g_k + (size_t)(b * S + k0) * D;

    for (int d0 = 0; d0 < D; d0 += 32) {
#pragma unroll
        for (int i = 0; i < 4; i++) {
            int idx = tid + i * 256;
            int r = idx >> 3, c = (idx & 7) * 4;
            float4 v = *reinterpret_cast<const float4*>(&Qg[(size_t)r * D + d0 + c]);
            __nv_bfloat16 h0, h1, h2, h3, l0, l1, l2, l3;
            split2(v.x, h0, l0); split2(v.y, h1, l1);
            split2(v.z, h2, l2); split2(v.w, h3, l3);
            *reinterpret_cast<__nv_bfloat162*>(&Qh[r][c])     = mk2(h0, h1);
            *reinterpret_cast<__nv_bfloat162*>(&Qh[r][c + 2]) = mk2(h2, h3);
            *reinterpret_cast<__nv_bfloat162*>(&Ql[r][c])     = mk2(l0, l1);
            *reinterpret_cast<__nv_bfloat162*>(&Ql[r][c + 2]) = mk2(l2, l3);
            float4 w = *reinterpret_cast<const float4*>(&Kg[(size_t)r * D + d0 + c]);
            split2(w.x, h0, l0); split2(w.y, h1, l1);
            split2(w.z, h2, l2); split2(w.w, h3, l3);
            *reinterpret_cast<__nv_bfloat162*>(&Kh[r][c])     = mk2(h0, h1);
            *reinterpret_cast<__nv_bfloat162*>(&Kh[r][c + 2]) = mk2(h2, h3);
            *reinterpret_cast<__nv_bfloat162*>(&Kl[r][c])     = mk2(l0, l1);
            *reinterpret_cast<__nv_bfloat162*>(&Kl[r][c + 2]) = mk2(l2, l3);
        }
        __syncthreads();

#pragma unroll
        for (int kc = 0; kc < 2; kc++) {
            int kk = kc * 16;
            uint32_t ah[4][4], al[4][4];
#pragma unroll
            for (int ma = 0; ma < 4; ma++) {
                int ar = wm * 64 + ma * 16 + qr;
                ah[ma][0] = *reinterpret_cast<const uint32_t*>(&Qh[ar][kk + 2 * qc]);
                ah[ma][1] = *reinterpret_cast<const uint32_t*>(&Qh[ar + 8][kk + 2 * qc]);
                ah[ma][2] = *reinterpret_cast<const uint32_t*>(&Qh[ar][kk + 8 + 2 * qc]);
                ah[ma][3] = *reinterpret_cast<const uint32_t*>(&Qh[ar + 8][kk + 8 + 2 * qc]);
                al[ma][0] = *reinterpret_cast<const uint32_t*>(&Ql[ar][kk + 2 * qc]);
                al[ma][1] = *reinterpret_cast<const uint32_t*>(&Ql[ar + 8][kk + 2 * qc]);
                al[ma][2] = *reinterpret_cast<const uint32_t*>(&Ql[ar][kk + 8 + 2 * qc]);
                al[ma][3] = *reinterpret_cast<const uint32_t*>(&Ql[ar + 8][kk + 8 + 2 * qc]);
            }
#pragma unroll
            for (int na = 0; na < 4; na++) {
                int nr = wn * 32 + na * 8 + qr;
                uint32_t bh0 = *reinterpret_cast<const uint32_t*>(&Kh[nr][kk + 2 * qc]);
                uint32_t bh1 = *reinterpret_cast<const uint32_t*>(&Kh[nr][kk + 8 + 2 * qc]);
                uint32_t bl0 = *reinterpret_cast<const uint32_t*>(&Kl[nr][kk + 2 * qc]);
                uint32_t bl1 = *reinterpret_cast<const uint32_t*>(&Kl[nr][kk + 8 + 2 * qc]);
#pragma unroll
                for (int ma = 0; ma < 4; ma++) {
                    mma16816(acc[ma][na], ah[ma][0], ah[ma][1], ah[ma][2], ah[ma][3], bh0, bh1);
                    mma16816(acc[ma][na], ah[ma][0], ah[ma][1], ah[ma][2], ah[ma][3], bl0, bl1);
                    mma16816(acc[ma][na], al[ma][0], al[ma][1], al[ma][2], al[ma][3], bh0, bh1);
                }
            }
        }
        __syncthreads();
    }

    const float scale = 0.125f;
#pragma unroll
    for (int ma = 0; ma < 4; ma++) {
#pragma unroll
        for (int na = 0; na < 4; na++) {
            int row = q0 + wm * 64 + ma * 16 + qr;
            int col = k0 + wn * 32 + na * 8 + 2 * qc;
            float2 v0, v1;
            v0.x = (col     <= row) ? acc[ma][na][0] * scale : 0.f;
            v0.y = (col + 1 <= row) ? acc[ma][na][1] * scale : 0.f;
            *reinterpret_cast<float2*>(&arow[(size_t)row * S + col]) = v0;
            int row2 = row + 8;
            v1.x = (col     <= row2) ? acc[ma][na][2] * scale : 0.f;
            v1.y = (col + 1 <= row2) ? acc[ma][na][3] * scale : 0.f;
            *reinterpret_cast<float2*>(&arow[(size_t)row2 * S + col]) = v1;
        }
    }
}

// ---------------------------------------------------------------------------
// Kernel 3: fused softmax + out. Block = 64 q-rows, 256 threads.
// Pass 1: streaming per-row max/Z. Pass 2: p = exp(s-m)/Z -> attn (fp32) and
// out += P @ V via bf16-split MMA. Grid (32, B).
// ---------------------------------------------------------------------------
__global__ __launch_bounds__(256) void softmax_out(
    float* __restrict__ attn, float* __restrict__ out)
{
    const int b = blockIdx.y, qt = blockIdx.x;
    const int q0 = qt * 64;
    float* arow = attn + (size_t)b * S * S;
    const float* Vt = g_vt + (size_t)b * D * S;

    const int tid = threadIdx.x, lane = tid & 31, wid = tid >> 5;
    const int rloc = tid >> 2;
    const int r = q0 + rloc;
    const int seg = tid & 3;
    const int nkt = qt + 1;     // 64-wide k tiles

    // ---- pass 1: row stats ----
    float m_run = -CUDART_INF_F, Z = 0.f;
    for (int t = 0; t < nkt; t++) {
        int kb = t * 64 + seg * 16;
        float vals[16];
        float tmax = -CUDART_INF_F;
        if (kb <= r) {
#pragma unroll
            for (int i = 0; i < 4; i++) {
                float4 v = *reinterpret_cast<const float4*>(
                    &arow[(size_t)r * S + kb + i * 4]);
                vals[i * 4 + 0] = v.x; vals[i * 4 + 1] = v.y;
                vals[i * 4 + 2] = v.z; vals[i * 4 + 3] = v.w;
            }
#pragma unroll
            for (int j = 0; j < 16; j++)
                if (kb + j <= r) tmax = fmaxf(tmax, vals[j]);
        }
        tmax = fmaxf(tmax, __shfl_xor_sync(0xffffffffu, tmax, 1));
        tmax = fmaxf(tmax, __shfl_xor_sync(0xffffffffu, tmax, 2));
        float m_new = fmaxf(m_run, tmax);
        float lsum = 0.f;
        if (kb <= r) {
#pragma unroll
            for (int j = 0; j < 16; j++)
                if (kb + j <= r) lsum += __expf(vals[j] - m_new);
        }
        lsum += __shfl_xor_sync(0xffffffffu, lsum, 1);
        lsum += __shfl_xor_sync(0xffffffffu, lsum, 2);
        Z = Z * __expf(m_run - m_new) + lsum;
        m_run = m_new;
    }
    const float invZ = 1.f / Z;

    // ---- pass 2: p + out MMA ----
    __shared__ __nv_bfloat16 Ph[64][72], Pl[64][72];
    __shared__ __nv_bfloat16 Vth[64][72], Vtl[64][72];

    const int wm = wid >> 1, wn = wid & 1;   // 4(m) x 2(n), warp tile 16x32
    const int qr = lane >> 2, qc = lane & 3;

    float oacc[4][4];
#pragma unroll
    for (int i = 0; i < 4; i++)
#pragma unroll
        for (int j = 0; j < 4; j++) oacc[i][j] = 0.f;

    for (int t = 0; t < nkt; t++) {
        int kb = t * 64 + seg * 16;
        if (kb <= r) {
#pragma unroll
            for (int i = 0; i < 4; i++) {
                float4 v = *reinterpret_cast<const float4*>(
                    &arow[(size_t)r * S + kb + i * 4]);
                float p0 = (kb + i * 4 + 0 <= r) ? __expf(v.x - m_run) * invZ : 0.f;
                float p1 = (kb + i * 4 + 1 <= r) ? __expf(v.y - m_run) * invZ : 0.f;
                float p2 = (kb + i * 4 + 2 <= r) ? __expf(v.z - m_run) * invZ : 0.f;
                float p3 = (kb + i * 4 + 3 <= r) ? __expf(v.w - m_run) * invZ : 0.f;
                *reinterpret_cast<float4*>(&arow[(size_t)r * S + kb + i * 4]) =
                    make_float4(p0, p1, p2, p3);
                __nv_bfloat16 h0, h1, h2, h3, l0, l1, l2, l3;
                split2(p0, h0, l0); split2(p1, h1, l1);
                split2(p2, h2, l2); split2(p3, h3, l3);
                int c = seg * 16 + i * 4;
                *reinterpret_cast<__nv_bfloat162*>(&Ph[rloc][c])     = mk2(h0, h1);
                *reinterpret_cast<__nv_bfloat162*>(&Ph[rloc][c + 2]) = mk2(h2, h3);
                *reinterpret_cast<__nv_bfloat162*>(&Pl[rloc][c])     = mk2(l0, l1);
                *reinterpret_cast<__nv_bfloat162*>(&Pl[rloc][c + 2]) = mk2(l2, l3);
            }
        } else {
            __nv_bfloat162 z2 = mk2(__float2bfloat16_rn(0.f), __float2bfloat16_rn(0.f));
#pragma unroll
            for (int i = 0; i < 4; i++) {
                int c = seg * 16 + i * 4;
                *reinterpret_cast<__nv_bfloat162*>(&Ph[rloc][c])     = z2;
                *reinterpret_cast<__nv_bfloat162*>(&Ph[rloc][c + 2]) = z2;
                *reinterpret_cast<__nv_bfloat162*>(&Pl[rloc][c])     = z2;
                *reinterpret_cast<__nv_bfloat162*>(&Pl[rloc][c + 2]) = z2;
            }
        }
        // V tile [64 d][64 keys] from pre-transposed g_vt
#pragma unroll
        for (int i = 0; i < 4; i++) {
            int idx = tid + i * 256;
            int dd = idx >> 4, c = (idx & 15) * 4;
            float4 v = *reinterpret_cast<const float4*>(
                &Vt[(size_t)dd * S + t * 64 + c]);
            __nv_bfloat16 h0, h1, h2, h3, l0, l1, l2, l3;
            split2(v.x, h0, l0); split2(v.y, h1, l1);
            split2(v.z, h2, l2); split2(v.w, h3, l3);
            *reinterpret_cast<__nv_bfloat162*>(&Vth[dd][c])     = mk2(h0, h1);
            *reinterpret_cast<__nv_bfloat162*>(&Vth[dd][c + 2]) = mk2(h2, h3);
            *reinterpret_cast<__nv_bfloat162*>(&Vtl[dd][c])     = mk2(l0, l1);
            *reinterpret_cast<__nv_bfloat162*>(&Vtl[dd][c + 2]) = mk2(l2, l3);
        }
        __syncthreads();

#pragma unroll
        for (int kc = 0; kc < 4; kc++) {
            int kk = kc * 16;
            int ar = wm * 16 + qr;
            uint32_t ah0 = *reinterpret_cast<const uint32_t*>(&Ph[ar][kk + 2 * qc]);
            uint32_t ah1 = *reinterpret_cast<const uint32_t*>(&Ph[ar + 8][kk + 2 * qc]);
            uint32_t ah2 = *reinterpret_cast<const uint32_t*>(&Ph[ar][kk + 8 + 2 * qc]);
            uint32_t ah3 = *reinterpret_cast<const uint32_t*>(&Ph[ar + 8][kk + 8 + 2 * qc]);
            uint32_t al0 = *reinterpret_cast<const uint32_t*>(&Pl[ar][kk + 2 * qc]);
            uint32_t al1 = *reinterpret_cast<const uint32_t*>(&Pl[ar + 8][kk + 2 * qc]);
            uint32_t al2 = *reinterpret_cast<const uint32_t*>(&Pl[ar][kk + 8 + 2 * qc]);
            uint32_t al3 = *reinterpret_cast<const uint32_t*>(&Pl[ar + 8][kk + 8 + 2 * qc]);
#pragma unroll
            for (int na = 0; na < 4; na++) {
                int nr = wn * 32 + na * 8 + qr;
                uint32_t bh0 = *reinterpret_cast<const uint32_t*>(&Vth[nr][kk + 2 * qc]);
                uint32_t bh1 = *reinterpret_cast<const uint32_t*>(&Vth[nr][kk + 8 + 2 * qc]);
                uint32_t bl0 = *reinterpret_cast<const uint32_t*>(&Vtl[nr][kk + 2 * qc]);
                uint32_t bl1 = *reinterpret_cast<const uint32_t*>(&Vtl[nr][kk + 8 + 2 * qc]);
                mma16816(oacc[na], ah0, ah1, ah2, ah3, bh0, bh1);
                mma16816(oacc[na], ah0, ah1, ah2, ah3, bl0, bl1);
                mma16816(oacc[na], al0, al1, al2, al3, bh0, bh1);
            }
        }
        __syncthreads();
    }

#pragma unroll
    for (int na = 0; na < 4; na++) {
        int row = q0 + wm * 16 + qr;
        int col = wn * 32 + na * 8 + 2 * qc;
        *reinterpret_cast<float2*>(&out[(size_t)(b * S + row) * D + col]) =
            make_float2(oacc[na][0], oacc[na][1]);
        *reinterpret_cast<float2*>(&out[(size_t)(b * S + row + 8) * D + col]) =
            make_float2(oacc[na][2], oacc[na][3]);
    }
}

// ---------------------------------------------------------------------------
extern "C" void kernel_launch(void* const* d_in, const int* in_sizes, int n_in,
                              void* d_out, int out_size)
{
    const float* seq = (const float*)d_in[0];
    const float* Wk  = (const float*)d_in[1];
    const float* Wq  = (const float*)d_in[2];
    const float* Wv  = (const float*)d_in[3];

    float* out  = (float*)d_out;                        // [B,S,D]
    float* attn = (float*)d_out + (size_t)B * S * D;    // [B,S,S]

    proj_mma<<<dim3(NROWS / 64, 1, 3), 256>>>(seq, Wk, Wq, Wv);
    scores_mma<<<dim3(S / 128, S / 128, B), 256>>>(attn);
    softmax_out<<<dim3(S / 64, B), 256>>>(attn, out);
}